// round 13
// baseline (speedup 1.0000x reference)
#include <cuda_runtime.h>

#define NN 4096
#define FF 256
#define EE 65536
#define ADJ_CAP 128
#define NBR_CAP 2048
#define ZW (NN/32)

// ---- device scratch ----
__device__ unsigned g_Z [(size_t)NN*ZW];          // 2 MB
__device__ int      g_adjcol[(size_t)NN*ADJ_CAP];
__device__ float    g_adjval[(size_t)NN*ADJ_CAP];
__device__ int      g_adjcnt[NN];
__device__ int      g_nbr [(size_t)NN*NBR_CAP];
__device__ float    g_nval[(size_t)NN*NBR_CAP];
__device__ int      g_D[NN];
__device__ int      g_Dr[NN];
__device__ float    g_sq[NN];
__device__ float    g_dthres;
// edge bucketing
__device__ int      g_ecnt[NN];
__device__ int      g_eoff[NN+1];
__device__ int      g_ecur[NN];
__device__ int2     g_edge[EE];     // {col, float_bits(w)}

// ---- fused: zero counters + squared norms ----
__global__ void k_init(const float* __restrict__ X) {
    int u = blockIdx.x;
    int tid = threadIdx.x;
    if (u < 16) g_ecnt[u*256 + tid] = 0;
    float x = X[(size_t)u*FF + tid];
    float v = x * x;
    __shared__ float red[8];
    for (int o = 16; o > 0; o >>= 1) v += __shfl_down_sync(0xffffffffu, v, o);
    if ((tid & 31) == 0) red[tid >> 5] = v;
    __syncthreads();
    if (tid == 0) {
        float t = 0.f;
        for (int i = 0; i < 8; i++) t += red[i];
        g_sq[u] = t;
    }
}

__global__ void k_hist(const int* __restrict__ ei) {
    int e = blockIdx.x*blockDim.x + threadIdx.x;
    if (e < EE) atomicAdd(&g_ecnt[ei[e]], 1);
}

__global__ void k_escan() {
    __shared__ int warpsum[32];
    int tid = threadIdx.x;
    int lane = tid & 31, wid = tid >> 5;
    int c0 = g_ecnt[tid*4+0], c1 = g_ecnt[tid*4+1],
        c2 = g_ecnt[tid*4+2], c3 = g_ecnt[tid*4+3];
    int s = c0 + c1 + c2 + c3;
    int v = s;
    #pragma unroll
    for (int o = 1; o < 32; o <<= 1) {
        int t = __shfl_up_sync(0xffffffffu, v, o);
        if (lane >= o) v += t;
    }
    if (lane == 31) warpsum[wid] = v;
    __syncthreads();
    if (wid == 0) {
        int w = warpsum[lane];
        #pragma unroll
        for (int o = 1; o < 32; o <<= 1) {
            int t = __shfl_up_sync(0xffffffffu, w, o);
            if (lane >= o) w += t;
        }
        warpsum[lane] = w;
    }
    __syncthreads();
    int base = (wid > 0 ? warpsum[wid-1] : 0) + (v - s);
    int run = base;
    g_eoff[tid*4+0] = run; g_ecur[tid*4+0] = run; run += c0;
    g_eoff[tid*4+1] = run; g_ecur[tid*4+1] = run; run += c1;
    g_eoff[tid*4+2] = run; g_ecur[tid*4+2] = run; run += c2;
    g_eoff[tid*4+3] = run; g_ecur[tid*4+3] = run; run += c3;
    if (tid == 1023) g_eoff[NN] = run;
}

__global__ void k_ebucket(const int* __restrict__ ei, const float* __restrict__ w) {
    int e = blockIdx.x*blockDim.x + threadIdx.x;
    if (e < EE) {
        int u = ei[e];
        int p = atomicAdd(&g_ecur[u], 1);
        g_edge[p] = make_int2(ei[EE + e], __float_as_int(w[e]));
    }
}

__device__ __forceinline__ void mask_scan_warp0(const unsigned* mask, int* woff,
                                                int lane, int wid) {
    if (wid == 0) {
        int c0 = __popc(mask[lane*4+0]);
        int c1 = __popc(mask[lane*4+1]);
        int c2 = __popc(mask[lane*4+2]);
        int c3 = __popc(mask[lane*4+3]);
        int s = c0+c1+c2+c3;
        int v = s;
        #pragma unroll
        for (int o = 1; o < 32; o <<= 1) {
            int t = __shfl_up_sync(0xffffffffu, v, o);
            if (lane >= o) v += t;
        }
        int run = v - s;
        woff[lane*4+0] = run; run += c0;
        woff[lane*4+1] = run; run += c1;
        woff[lane*4+2] = run; run += c2;
        woff[lane*4+3] = run; run += c3;
        if (lane == 31) woff[128] = run;
    }
}

__global__ void k_build_adj() {
    int u   = blockIdx.x;
    int tid = threadIdx.x;
    int lane = tid & 31, wid = tid >> 5;

    __shared__ __align__(16) float srow[NN];
    __shared__ unsigned mask[128];
    __shared__ int      woff[129];

    float4* s4 = (float4*)srow;
    float4 z = make_float4(0.f,0.f,0.f,0.f);
    #pragma unroll
    for (int it = 0; it < 4; it++) s4[tid + it*256] = z;
    if (tid < 128) mask[tid] = 0u;
    __syncthreads();

    int eb = g_eoff[u], ee = g_eoff[u+1];
    for (int p = eb + tid; p < ee; p += 256) {
        int2 ev = g_edge[p];
        int v = ev.x;
        atomicAdd(&srow[v], __int_as_float(ev.y));
        atomicOr(&mask[v >> 5], 1u << (v & 31));
    }
    if (tid == 0) {
        atomicAdd(&srow[u], 1.f);
        atomicOr(&mask[u >> 5], 1u << (u & 31));
    }
    __syncthreads();

    mask_scan_warp0(mask, woff, lane, wid);
    __syncthreads();
    int tot = woff[128];
    if (tid == 0) {
        g_adjcnt[u] = min(tot, ADJ_CAP);
        g_D[u] = tot - 1;
    }
    if (tid < 128) {
        unsigned mw = mask[tid];
        int pos = woff[tid];
        int base = tid << 5;
        while (mw) {
            int b = __ffs(mw) - 1;
            mw &= mw - 1;
            if (pos < ADJ_CAP) {
                int col = base + b;
                g_adjcol[(size_t)u*ADJ_CAP + pos] = col;
                g_adjval[(size_t)u*ADJ_CAP + pos] = fminf(srow[col], 1.f);
            }
            pos++;
        }
    }
}

// ---- spgemm (+ folded stats block) ----
__global__ void k_spgemm() {
    if (blockIdx.x == NN) {
        __shared__ double s1[8], s2s[8];
        double s = 0.0, sq = 0.0;
        for (int i = threadIdx.x; i < NN; i += blockDim.x) {
            double d = (double)g_D[i];
            s += d; sq += d*d;
        }
        for (int o = 16; o > 0; o >>= 1) {
            s  += __shfl_down_sync(0xffffffffu, s,  o);
            sq += __shfl_down_sync(0xffffffffu, sq, o);
        }
        int lane = threadIdx.x & 31, wid = threadIdx.x >> 5;
        if (lane == 0) { s1[wid] = s; s2s[wid] = sq; }
        __syncthreads();
        if (threadIdx.x == 0) {
            double S = 0.0, SQ = 0.0;
            for (int i = 0; i < 8; i++) { S += s1[i]; SQ += s2s[i]; }
            double mean = S / NN;
            double var  = SQ / NN - mean*mean;
            if (var < 0.0) var = 0.0;
            g_dthres = (float)(mean + 2.0 * sqrt(var));
        }
        return;
    }

    int u   = blockIdx.x;
    int tid = threadIdx.x;
    int lane = tid & 31, wid = tid >> 5;
    int half = lane >> 4;
    int sl   = lane & 15;

    __shared__ __align__(16) float acc[NN];
    __shared__ unsigned mask[128];
    __shared__ int      woff[129];
    __shared__ int      smu;

    float4* a4 = (float4*)acc;
    float4 z = make_float4(0.f,0.f,0.f,0.f);
    #pragma unroll
    for (int it = 0; it < 4; it++) a4[tid + it*256] = z;
    if (tid < 128) mask[tid] = 0u;
    if (tid == 0) smu = g_adjcnt[u];
    __syncthreads();
    int mu = smu;

    for (int ki = wid*2 + half; ki < mu; ki += 16) {
        int   k  = g_adjcol[(size_t)u*ADJ_CAP + ki];
        float vu = g_adjval[(size_t)u*ADJ_CAP + ki];
        int cnt  = g_adjcnt[k];
        const int*   kc = g_adjcol + (size_t)k*ADJ_CAP;
        const float* kv = g_adjval + (size_t)k*ADJ_CAP;
        for (int q = sl; q < cnt; q += 16) {
            int   j = kc[q];
            float v = vu * kv[q];
            atomicAdd(&acc[j], v);
            atomicOr(&mask[j >> 5], 1u << (j & 31));
        }
    }
    __syncthreads();
    if (tid == 0) mask[u >> 5] &= ~(1u << (u & 31));   // setdiag(0)
    __syncthreads();

    mask_scan_warp0(mask, woff, lane, wid);
    __syncthreads();
    if (tid == 0) g_Dr[u] = woff[128];
    if (tid < 128) {
        unsigned mw = mask[tid];
        int pos = woff[tid];
        int base = tid << 5;
        while (mw) {
            int b = __ffs(mw) - 1;
            mw &= mw - 1;
            if (pos < NBR_CAP) {
                int col = base + b;
                g_nbr [(size_t)u*NBR_CAP + pos] = col;
                g_nval[(size_t)u*NBR_CAP + pos] = acc[col];
            }
            pos++;
        }
    }
}

// ---- build Z bitmask per row: 4 neighbors per warp (8 loads in flight/lane) ----
__global__ void k_zbuild(const float* __restrict__ X) {
    int u   = blockIdx.x;
    int tid = threadIdx.x;
    int lane = tid & 31, wid = tid >> 5;

    __shared__ int      scol [NBR_CAP];
    __shared__ __align__(16) float sdist[NBR_CAP];
    __shared__ __align__(16) float xu[FF];
    __shared__ unsigned zw[ZW];

    int   D  = g_D[u], Dr = g_Dr[u];
    float dthres = g_dthres;
    unsigned* Zrow = g_Z + (size_t)u*ZW;

    bool highD = ((float)D > dthres);
    if (highD) {
        for (int w = tid; w < ZW; w += 256) zw[w] = 0xffffffffu;
        __syncthreads();
        int cnt = g_adjcnt[u];
        for (int p = tid; p < cnt; p += 256) {
            int c = g_adjcol[(size_t)u*ADJ_CAP + p];
            if (c != u) atomicAnd(&zw[c >> 5], ~(1u << (c & 31)));
        }
        __syncthreads();
        for (int w = tid; w < ZW; w += 256) Zrow[w] = zw[w];
        return;
    }
    if (2*D > Dr) {
        for (int w = tid; w < ZW; w += 256) Zrow[w] = 0u;
        return;
    }
    int m = min(Dr, NBR_CAP);
    int nz = Dr - 2*D;
    if (nz == 0) {
        for (int w = tid; w < ZW; w += 256) zw[w] = 0u;
        __syncthreads();
        for (int p = tid; p < m; p += 256) {
            int c = g_nbr[(size_t)u*NBR_CAP + p];
            atomicOr(&zw[c >> 5], 1u << (c & 31));
        }
        __syncthreads();
        for (int w = tid; w < ZW; w += 256) Zrow[w] = zw[w];
        return;
    }

    // --- sparse branch ---
    xu[tid] = X[(size_t)u*FF + tid];
    for (int p = tid; p < m; p += 256) scol[p] = g_nbr[(size_t)u*NBR_CAP + p];
    for (int w = tid; w < ZW; w += 256) zw[w] = 0u;
    __syncthreads();

    float4 ax0 = *(const float4*)&xu[lane*4];
    float4 ax1 = *(const float4*)&xu[128 + lane*4];
    float squ = g_sq[u];

    // 8 warps x 4 neighbors each -> 8 independent float4 loads in flight per lane
    for (int nb = wid*4; nb < m; nb += 32) {
        int j0 = scol[nb];
        int j1 = (nb+1 < m) ? scol[nb+1] : j0;
        int j2 = (nb+2 < m) ? scol[nb+2] : j0;
        int j3 = (nb+3 < m) ? scol[nb+3] : j0;
        const float4* p0 = (const float4*)(X + (size_t)j0*FF);
        const float4* p1 = (const float4*)(X + (size_t)j1*FF);
        const float4* p2 = (const float4*)(X + (size_t)j2*FF);
        const float4* p3 = (const float4*)(X + (size_t)j3*FF);
        float4 a0 = p0[lane], a1 = p0[lane+32];
        float4 b0 = p1[lane], b1 = p1[lane+32];
        float4 c0 = p2[lane], c1 = p2[lane+32];
        float4 d0 = p3[lane], d1 = p3[lane+32];
        float d_a = a0.x*ax0.x + a0.y*ax0.y + a0.z*ax0.z + a0.w*ax0.w
                  + a1.x*ax1.x + a1.y*ax1.y + a1.z*ax1.z + a1.w*ax1.w;
        float d_b = b0.x*ax0.x + b0.y*ax0.y + b0.z*ax0.z + b0.w*ax0.w
                  + b1.x*ax1.x + b1.y*ax1.y + b1.z*ax1.z + b1.w*ax1.w;
        float d_c = c0.x*ax0.x + c0.y*ax0.y + c0.z*ax0.z + c0.w*ax0.w
                  + c1.x*ax1.x + c1.y*ax1.y + c1.z*ax1.z + c1.w*ax1.w;
        float d_d = d0.x*ax0.x + d0.y*ax0.y + d0.z*ax0.z + d0.w*ax0.w
                  + d1.x*ax1.x + d1.y*ax1.y + d1.z*ax1.z + d1.w*ax1.w;
        #pragma unroll
        for (int o = 16; o > 0; o >>= 1) {
            d_a += __shfl_down_sync(0xffffffffu, d_a, o);
            d_b += __shfl_down_sync(0xffffffffu, d_b, o);
            d_c += __shfl_down_sync(0xffffffffu, d_c, o);
            d_d += __shfl_down_sync(0xffffffffu, d_d, o);
        }
        if (lane == 0) {
            sdist[nb] = squ + g_sq[j0] - 2.f * d_a;
            if (nb+1 < m) sdist[nb+1] = squ + g_sq[j1] - 2.f * d_b;
            if (nb+2 < m) sdist[nb+2] = squ + g_sq[j2] - 2.f * d_c;
            if (nb+3 < m) sdist[nb+3] = squ + g_sq[j3] - 2.f * d_d;
        }
    }
    __syncthreads();

    for (int i = tid; i < m; i += 256) {
        float di = sdist[i];
        int rank = 0;
        for (int j = 0; j < m; j++) {
            float dj = sdist[j];
            rank += (dj > di) || (dj == di && j < i);
        }
        if (rank < nz) {
            int c = scol[i];
            atomicOr(&zw[c >> 5], 1u << (c & 31));
        }
    }
    __syncthreads();
    for (int w = tid; w < ZW; w += 256) Zrow[w] = zw[w];
}

__device__ __forceinline__ int bsearch_col(const int* __restrict__ cols, int n, int v) {
    int lo = 0, hi = n;
    while (lo < hi) {
        int mid = (lo + hi) >> 1;
        if (cols[mid] < v) lo = mid + 1; else hi = mid;
    }
    return (lo < n && cols[lo] == v) ? lo : -1;
}

__global__ void k_edge(const int* __restrict__ ei, const float* __restrict__ w,
                       const float* __restrict__ t1, const float* __restrict__ t2,
                       float* __restrict__ out) {
    int e = blockIdx.x*blockDim.x + threadIdx.x;
    if (e >= EE) return;
    int u = ei[e], v = ei[EE + e];
    float a = 0.f, a2 = 0.f;
    if (v != u) {
        int c = g_adjcnt[u];
        int p = bsearch_col(g_adjcol + (size_t)u*ADJ_CAP, c, v);
        if (p >= 0) a = g_adjval[(size_t)u*ADJ_CAP + p];
        int m = min(g_Dr[u], NBR_CAP);
        int q = bsearch_col(g_nbr + (size_t)u*NBR_CAP, m, v);
        if (q >= 0) a2 = g_nval[(size_t)u*NBR_CAP + q];
    }
    unsigned zword = g_Z[(size_t)u*ZW + (v >> 5)];
    bool z = (zword >> (v & 31)) & 1u;
    float adj = z ? 0.f : (a2 - a);
    float val = t1[0]*w[e] + t2[0]*adj;
    out[e] = fmaxf(val, 0.f);
}

extern "C" void kernel_launch(void* const* d_in, const int* in_sizes, int n_in,
                              void* d_out, int out_size) {
    const int*   ei = (const int*)  d_in[0];
    const float* w  = (const float*)d_in[1];
    const float* X  = (const float*)d_in[2];
    const float* t1 = (const float*)d_in[3];
    const float* t2 = (const float*)d_in[4];
    float* out = (float*)d_out;

    k_init     <<<NN, 256>>>(X);
    k_hist     <<<EE/256, 256>>>(ei);
    k_escan    <<<1, 1024>>>();
    k_ebucket  <<<EE/256, 256>>>(ei, w);
    k_build_adj<<<NN, 256>>>();
    k_spgemm   <<<NN+1, 256>>>();
    k_zbuild   <<<NN, 256>>>(X);
    k_edge     <<<EE/256, 256>>>(ei, w, t1, t2, out);
}

// round 14
// speedup vs baseline: 1.0237x; 1.0237x over previous
#include <cuda_runtime.h>

#define NN 4096
#define FF 256
#define EE 65536
#define ADJ_CAP 128
#define NBR_CAP 2048
#define ZW (NN/32)

// ---- device scratch ----
__device__ unsigned g_Z [(size_t)NN*ZW];          // 2 MB
__device__ int      g_adjcol[(size_t)NN*ADJ_CAP];
__device__ float    g_adjval[(size_t)NN*ADJ_CAP];
__device__ int      g_adjcnt[NN];
__device__ int      g_nbr [(size_t)NN*NBR_CAP];
__device__ float    g_nval[(size_t)NN*NBR_CAP];
__device__ int      g_D[NN];
__device__ int      g_Dr[NN];
__device__ float    g_sq[NN];
__device__ float    g_dthres;
// edge bucketing
__device__ int      g_ecnt[NN];
__device__ int      g_eoff[NN+1];
__device__ int      g_ecur[NN];
__device__ int2     g_edge[EE];     // {col, float_bits(w)}

// ---- fused: zero counters + squared norms ----
__global__ void k_init(const float* __restrict__ X) {
    int u = blockIdx.x;
    int tid = threadIdx.x;
    if (u < 16) g_ecnt[u*256 + tid] = 0;
    float x = X[(size_t)u*FF + tid];
    float v = x * x;
    __shared__ float red[8];
    for (int o = 16; o > 0; o >>= 1) v += __shfl_down_sync(0xffffffffu, v, o);
    if ((tid & 31) == 0) red[tid >> 5] = v;
    __syncthreads();
    if (tid == 0) {
        float t = 0.f;
        for (int i = 0; i < 8; i++) t += red[i];
        g_sq[u] = t;
    }
}

__global__ void k_hist(const int* __restrict__ ei) {
    int e = blockIdx.x*blockDim.x + threadIdx.x;
    if (e < EE) atomicAdd(&g_ecnt[ei[e]], 1);
}

__global__ void k_escan() {
    __shared__ int warpsum[32];
    int tid = threadIdx.x;
    int lane = tid & 31, wid = tid >> 5;
    int c0 = g_ecnt[tid*4+0], c1 = g_ecnt[tid*4+1],
        c2 = g_ecnt[tid*4+2], c3 = g_ecnt[tid*4+3];
    int s = c0 + c1 + c2 + c3;
    int v = s;
    #pragma unroll
    for (int o = 1; o < 32; o <<= 1) {
        int t = __shfl_up_sync(0xffffffffu, v, o);
        if (lane >= o) v += t;
    }
    if (lane == 31) warpsum[wid] = v;
    __syncthreads();
    if (wid == 0) {
        int w = warpsum[lane];
        #pragma unroll
        for (int o = 1; o < 32; o <<= 1) {
            int t = __shfl_up_sync(0xffffffffu, w, o);
            if (lane >= o) w += t;
        }
        warpsum[lane] = w;
    }
    __syncthreads();
    int base = (wid > 0 ? warpsum[wid-1] : 0) + (v - s);
    int run = base;
    g_eoff[tid*4+0] = run; g_ecur[tid*4+0] = run; run += c0;
    g_eoff[tid*4+1] = run; g_ecur[tid*4+1] = run; run += c1;
    g_eoff[tid*4+2] = run; g_ecur[tid*4+2] = run; run += c2;
    g_eoff[tid*4+3] = run; g_ecur[tid*4+3] = run; run += c3;
    if (tid == 1023) g_eoff[NN] = run;
}

__global__ void k_ebucket(const int* __restrict__ ei, const float* __restrict__ w) {
    int e = blockIdx.x*blockDim.x + threadIdx.x;
    if (e < EE) {
        int u = ei[e];
        int p = atomicAdd(&g_ecur[u], 1);
        g_edge[p] = make_int2(ei[EE + e], __float_as_int(w[e]));
    }
}

__device__ __forceinline__ void mask_scan_warp0(const unsigned* mask, int* woff,
                                                int lane, int wid) {
    if (wid == 0) {
        int c0 = __popc(mask[lane*4+0]);
        int c1 = __popc(mask[lane*4+1]);
        int c2 = __popc(mask[lane*4+2]);
        int c3 = __popc(mask[lane*4+3]);
        int s = c0+c1+c2+c3;
        int v = s;
        #pragma unroll
        for (int o = 1; o < 32; o <<= 1) {
            int t = __shfl_up_sync(0xffffffffu, v, o);
            if (lane >= o) v += t;
        }
        int run = v - s;
        woff[lane*4+0] = run; run += c0;
        woff[lane*4+1] = run; run += c1;
        woff[lane*4+2] = run; run += c2;
        woff[lane*4+3] = run; run += c3;
        if (lane == 31) woff[128] = run;
    }
}

__global__ void k_build_adj() {
    int u   = blockIdx.x;
    int tid = threadIdx.x;
    int lane = tid & 31, wid = tid >> 5;

    __shared__ float    srow[NN];
    __shared__ unsigned mask[128];
    __shared__ int      woff[129];

    float4* s4 = (float4*)srow;
    float4 z = make_float4(0.f,0.f,0.f,0.f);
    #pragma unroll
    for (int it = 0; it < 4; it++) s4[tid + it*256] = z;
    if (tid < 128) mask[tid] = 0u;
    __syncthreads();

    int eb = g_eoff[u], ee = g_eoff[u+1];
    for (int p = eb + tid; p < ee; p += 256) {
        int2 ev = g_edge[p];
        int v = ev.x;
        atomicAdd(&srow[v], __int_as_float(ev.y));
        atomicOr(&mask[v >> 5], 1u << (v & 31));
    }
    // diag in same region (atomic, order-independent)
    if (tid == 0) {
        atomicAdd(&srow[u], 1.f);
        atomicOr(&mask[u >> 5], 1u << (u & 31));
    }
    __syncthreads();

    mask_scan_warp0(mask, woff, lane, wid);
    __syncthreads();
    int tot = woff[128];
    if (tid == 0) {
        g_adjcnt[u] = min(tot, ADJ_CAP);
        g_D[u] = tot - 1;
    }
    // mask-guided compaction: thread per 32-col word, pop set bits
    if (tid < 128) {
        unsigned mw = mask[tid];
        int pos = woff[tid];
        int base = tid << 5;
        while (mw) {
            int b = __ffs(mw) - 1;
            mw &= mw - 1;
            if (pos < ADJ_CAP) {
                int col = base + b;
                g_adjcol[(size_t)u*ADJ_CAP + pos] = col;
                g_adjval[(size_t)u*ADJ_CAP + pos] = fminf(srow[col], 1.f);
            }
            pos++;
        }
    }
}

// ---- spgemm (+ folded stats block) ----
__global__ void k_spgemm() {
    if (blockIdx.x == NN) {
        // stats: d_thres = mean(D) + 2*std(D); g_D written by k_build_adj (done)
        __shared__ double s1[8], s2s[8];
        double s = 0.0, sq = 0.0;
        for (int i = threadIdx.x; i < NN; i += blockDim.x) {
            double d = (double)g_D[i];
            s += d; sq += d*d;
        }
        for (int o = 16; o > 0; o >>= 1) {
            s  += __shfl_down_sync(0xffffffffu, s,  o);
            sq += __shfl_down_sync(0xffffffffu, sq, o);
        }
        int lane = threadIdx.x & 31, wid = threadIdx.x >> 5;
        if (lane == 0) { s1[wid] = s; s2s[wid] = sq; }
        __syncthreads();
        if (threadIdx.x == 0) {
            double S = 0.0, SQ = 0.0;
            for (int i = 0; i < 8; i++) { S += s1[i]; SQ += s2s[i]; }
            double mean = S / NN;
            double var  = SQ / NN - mean*mean;
            if (var < 0.0) var = 0.0;
            g_dthres = (float)(mean + 2.0 * sqrt(var));
        }
        return;
    }

    int u   = blockIdx.x;
    int tid = threadIdx.x;
    int lane = tid & 31, wid = tid >> 5;
    int half = lane >> 4;          // 0 or 1
    int sl   = lane & 15;          // sub-lane

    __shared__ float    acc[NN];
    __shared__ unsigned mask[128];
    __shared__ int      woff[129];
    __shared__ int      smu;

    float4* a4 = (float4*)acc;
    float4 z = make_float4(0.f,0.f,0.f,0.f);
    #pragma unroll
    for (int it = 0; it < 4; it++) a4[tid + it*256] = z;
    if (tid < 128) mask[tid] = 0u;
    if (tid == 0) smu = g_adjcnt[u];
    __syncthreads();
    int mu = smu;

    // half-warp-per-k product enumeration (16 lanes per neighbor row)
    for (int ki = wid*2 + half; ki < mu; ki += 16) {
        int   k  = g_adjcol[(size_t)u*ADJ_CAP + ki];
        float vu = g_adjval[(size_t)u*ADJ_CAP + ki];
        int cnt  = g_adjcnt[k];
        const int*   kc = g_adjcol + (size_t)k*ADJ_CAP;
        const float* kv = g_adjval + (size_t)k*ADJ_CAP;
        for (int q = sl; q < cnt; q += 16) {
            int   j = kc[q];
            float v = vu * kv[q];
            atomicAdd(&acc[j], v);
            atomicOr(&mask[j >> 5], 1u << (j & 31));
        }
    }
    __syncthreads();
    if (tid == 0) mask[u >> 5] &= ~(1u << (u & 31));   // setdiag(0)
    __syncthreads();

    mask_scan_warp0(mask, woff, lane, wid);
    __syncthreads();
    if (tid == 0) g_Dr[u] = woff[128];
    if (tid < 128) {
        unsigned mw = mask[tid];
        int pos = woff[tid];
        int base = tid << 5;
        while (mw) {
            int b = __ffs(mw) - 1;
            mw &= mw - 1;
            if (pos < NBR_CAP) {
                int col = base + b;
                g_nbr [(size_t)u*NBR_CAP + pos] = col;
                g_nval[(size_t)u*NBR_CAP + pos] = acc[col];
            }
            pos++;
        }
    }
}

// ---- build Z bitmask per row ----
__global__ void k_zbuild(const float* __restrict__ X) {
    int u   = blockIdx.x;
    int tid = threadIdx.x;
    int lane = tid & 31, wid = tid >> 5;

    __shared__ int      scol [NBR_CAP];
    __shared__ float    sdist[NBR_CAP];
    __shared__ float    xu[FF];
    __shared__ unsigned zw[ZW];

    int   D  = g_D[u], Dr = g_Dr[u];
    float dthres = g_dthres;
    unsigned* Zrow = g_Z + (size_t)u*ZW;

    bool highD = ((float)D > dthres);
    if (highD) {
        for (int w = tid; w < ZW; w += 256) zw[w] = 0xffffffffu;
        __syncthreads();
        int cnt = g_adjcnt[u];
        for (int p = tid; p < cnt; p += 256) {
            int c = g_adjcol[(size_t)u*ADJ_CAP + p];
            if (c != u) atomicAnd(&zw[c >> 5], ~(1u << (c & 31)));
        }
        __syncthreads();
        for (int w = tid; w < ZW; w += 256) Zrow[w] = zw[w];
        return;
    }
    if (2*D > Dr) {
        for (int w = tid; w < ZW; w += 256) Zrow[w] = 0u;
        return;
    }
    int m = min(Dr, NBR_CAP);
    int nz = Dr - 2*D;
    if (nz == 0) {
        for (int w = tid; w < ZW; w += 256) zw[w] = 0u;
        __syncthreads();
        for (int p = tid; p < m; p += 256) {
            int c = g_nbr[(size_t)u*NBR_CAP + p];
            atomicOr(&zw[c >> 5], 1u << (c & 31));
        }
        __syncthreads();
        for (int w = tid; w < ZW; w += 256) Zrow[w] = zw[w];
        return;
    }

    // --- sparse branch ---
    xu[tid] = X[(size_t)u*FF + tid];
    for (int p = tid; p < m; p += 256) scol[p] = g_nbr[(size_t)u*NBR_CAP + p];
    for (int w = tid; w < ZW; w += 256) zw[w] = 0u;
    __syncthreads();

    float4 ax0 = *(const float4*)&xu[lane*4];
    float4 ax1 = *(const float4*)&xu[128 + lane*4];
    float squ = g_sq[u];

    for (int nb = wid*2; nb < m; nb += 16) {
        int j0 = scol[nb];
        int j1 = (nb+1 < m) ? scol[nb+1] : j0;
        const float4* xa = (const float4*)(X + (size_t)j0*FF);
        const float4* xb = (const float4*)(X + (size_t)j1*FF);
        float4 a0 = xa[lane],      b0 = xb[lane];
        float4 a1 = xa[lane + 32], b1 = xb[lane + 32];
        float da = a0.x*ax0.x + a0.y*ax0.y + a0.z*ax0.z + a0.w*ax0.w
                 + a1.x*ax1.x + a1.y*ax1.y + a1.z*ax1.z + a1.w*ax1.w;
        float db = b0.x*ax0.x + b0.y*ax0.y + b0.z*ax0.z + b0.w*ax0.w
                 + b1.x*ax1.x + b1.y*ax1.y + b1.z*ax1.z + b1.w*ax1.w;
        #pragma unroll
        for (int o = 16; o > 0; o >>= 1) {
            da += __shfl_down_sync(0xffffffffu, da, o);
            db += __shfl_down_sync(0xffffffffu, db, o);
        }
        if (lane == 0) {
            sdist[nb] = squ + g_sq[j0] - 2.f * da;
            if (nb+1 < m) sdist[nb+1] = squ + g_sq[j1] - 2.f * db;
        }
    }
    __syncthreads();

    for (int i = tid; i < m; i += 256) {
        float di = sdist[i];
        int rank = 0;
        for (int j = 0; j < m; j++) {
            float dj = sdist[j];
            rank += (dj > di) || (dj == di && j < i);
        }
        if (rank < nz) {
            int c = scol[i];
            atomicOr(&zw[c >> 5], 1u << (c & 31));
        }
    }
    __syncthreads();
    for (int w = tid; w < ZW; w += 256) Zrow[w] = zw[w];
}

__device__ __forceinline__ int bsearch_col(const int* __restrict__ cols, int n, int v) {
    int lo = 0, hi = n;
    while (lo < hi) {
        int mid = (lo + hi) >> 1;
        if (cols[mid] < v) lo = mid + 1; else hi = mid;
    }
    return (lo < n && cols[lo] == v) ? lo : -1;
}

__global__ void k_edge(const int* __restrict__ ei, const float* __restrict__ w,
                       const float* __restrict__ t1, const float* __restrict__ t2,
                       float* __restrict__ out) {
    int e = blockIdx.x*blockDim.x + threadIdx.x;
    if (e >= EE) return;
    int u = ei[e], v = ei[EE + e];
    float a = 0.f, a2 = 0.f;
    if (v != u) {
        int c = g_adjcnt[u];
        int p = bsearch_col(g_adjcol + (size_t)u*ADJ_CAP, c, v);
        if (p >= 0) a = g_adjval[(size_t)u*ADJ_CAP + p];
        int m = min(g_Dr[u], NBR_CAP);
        int q = bsearch_col(g_nbr + (size_t)u*NBR_CAP, m, v);
        if (q >= 0) a2 = g_nval[(size_t)u*NBR_CAP + q];
    }
    unsigned zword = g_Z[(size_t)u*ZW + (v >> 5)];
    bool z = (zword >> (v & 31)) & 1u;
    float adj = z ? 0.f : (a2 - a);
    float val = t1[0]*w[e] + t2[0]*adj;
    out[e] = fmaxf(val, 0.f);
}

extern "C" void kernel_launch(void* const* d_in, const int* in_sizes, int n_in,
                              void* d_out, int out_size) {
    const int*   ei = (const int*)  d_in[0];
    const float* w  = (const float*)d_in[1];
    const float* X  = (const float*)d_in[2];
    const float* t1 = (const float*)d_in[3];
    const float* t2 = (const float*)d_in[4];
    float* out = (float*)d_out;

    k_init     <<<NN, 256>>>(X);
    k_hist     <<<EE/256, 256>>>(ei);
    k_escan    <<<1, 1024>>>();
    k_ebucket  <<<EE/256, 256>>>(ei, w);
    k_build_adj<<<NN, 256>>>();
    k_spgemm   <<<NN+1, 256>>>();
    k_zbuild   <<<NN, 256>>>(X);
    k_edge     <<<EE/256, 256>>>(ei, w, t1, t2, out);
}